// round 5
// baseline (speedup 1.0000x reference)
#include <cuda_runtime.h>
#include <cuda_fp16.h>

#define N_I 500000
#define N_H 200000
#define F_I 32
#define F_H 16
#define EF  8
#define E1  2000000
#define E2  2000000

// Packed per-source-node record, 32 bytes (one L2 sector) per node:
//   floats [0..3] : y[0..7] as 8 x fp16 (packed pairs)
//   float  [4]    : z (fp32);  [5..7] pad
__device__ __align__(32) float g_rec_h[(size_t)N_H * 8];
__device__ __align__(32) float g_rec_i[(size_t)N_I * 8];

__device__ __forceinline__ float pack2h(float a, float b) {
    __half2 h = __floats2half2_rn(a, b);
    return __uint_as_float(*reinterpret_cast<unsigned*>(&h));
}

// ==========================================================================
// K1: zero the output (500k floats) + house precompute.
//   blocks [0, ZERO_BLOCKS): zero out ; [ZERO_BLOCKS, +BLOCKS_H): house pre
// ==========================================================================
#define ZERO_BLOCKS 489                       // ceil(125000 float4 / 256)
#define BLOCKS_H ((N_H + 255) / 256)          // 782
#define STRIDE_H 17

__global__ void __launch_bounds__(256)
k1_house_zero(const float* __restrict__ x_house,
              const float* __restrict__ W_edge_h,  // [F_H, EF]
              const float* __restrict__ b_edge_h,  // [F_H]
              float* __restrict__ out)
{
    int t = threadIdx.x;
    if (blockIdx.x < ZERO_BLOCKS) {
        int i = blockIdx.x * 256 + t;               // float4 index
        if (i < N_I / 4)
            reinterpret_cast<float4*>(out)[i] = make_float4(0.f, 0.f, 0.f, 0.f);
        return;
    }

    __shared__ float sx[256 * STRIDE_H];            // 17.4 KB
    __shared__ float sW[F_H * EF];
    __shared__ float sb[F_H];
    if (t < F_H * EF) sW[t] = W_edge_h[t];
    if (t < F_H)      sb[t] = b_edge_h[t];

    int base = (blockIdx.x - ZERO_BLOCKS) * 256;
    const float4* x4 = reinterpret_cast<const float4*>(x_house);
    long gbase = (long)base * (F_H / 4);
    long gmax  = (long)N_H * (F_H / 4);
#pragma unroll
    for (int i = 0; i < 4; i++) {
        long gidx = gbase + t + i * 256;
        if (gidx < gmax) {
            float4 v = x4[gidx];
            int loc = t + i * 256;
            int row = loc >> 2;                     // 4 float4 per row
            int col = loc & 3;
            float* p = sx + row * STRIDE_H + col * 4;
            p[0] = v.x; p[1] = v.y; p[2] = v.z; p[3] = v.w;
        }
    }
    __syncthreads();

    int n = base + t;
    if (n >= N_H) return;

    const float* xr = sx + t * STRIDE_H;
    float y[EF];
#pragma unroll
    for (int k = 0; k < EF; k++) y[k] = 0.f;
    float z = 0.f;
#pragma unroll
    for (int f = 0; f < F_H; f++) {
        float xf = xr[f];
#pragma unroll
        for (int k = 0; k < EF; k++) y[k] = fmaf(xf, sW[f*EF + k], y[k]);
        z = fmaf(xf, sb[f], z);
    }

    float4* ro = reinterpret_cast<float4*>(g_rec_h + (size_t)n * 8);
    ro[0] = make_float4(pack2h(y[0], y[1]), pack2h(y[2], y[3]),
                        pack2h(y[4], y[5]), pack2h(y[6], y[7]));
    ro[1] = make_float4(z, 0.f, 0.f, 0.f);
}

// ==========================================================================
// Edge message body: msg = ea[e].y[src] + z[src]; atomic add to out[dst].
// ==========================================================================
__device__ __forceinline__ void
edge_body(const float* __restrict__ ea, const int* __restrict__ src,
          const int* __restrict__ dst, const float* __restrict__ rec,
          float* __restrict__ out, int e)
{
    int s = __ldg(src + e);
    int d = __ldg(dst + e);

    const float4* ar = reinterpret_cast<const float4*>(ea + (size_t)e * EF);
    float4 a0 = __ldg(ar);
    float4 a1 = __ldg(ar + 1);

    float4 v = __ldg(reinterpret_cast<const float4*>(rec + (size_t)s * 8));
    float  z = __ldg(rec + (size_t)s * 8 + 4);     // same 32B sector

    float2 f01 = __half22float2(*reinterpret_cast<__half2*>(&v.x));
    float2 f23 = __half22float2(*reinterpret_cast<__half2*>(&v.y));
    float2 f45 = __half22float2(*reinterpret_cast<__half2*>(&v.z));
    float2 f67 = __half22float2(*reinterpret_cast<__half2*>(&v.w));

    float m = z;
    m = fmaf(a0.x, f01.x, m);
    m = fmaf(a0.y, f01.y, m);
    m = fmaf(a0.z, f23.x, m);
    m = fmaf(a0.w, f23.y, m);
    m = fmaf(a1.x, f45.x, m);
    m = fmaf(a1.y, f45.y, m);
    m = fmaf(a1.z, f67.x, m);
    m = fmaf(a1.w, f67.y, m);

    atomicAdd(out + d, m);
}

// ==========================================================================
// K2 (fused, independent block ranges, 128-thread blocks):
//   blocks [0, PRE_I_BLOCKS): indivi precompute + root atomicAdd into out
//   blocks [PRE_I_BLOCKS, +EDGE1_BLOCKS): edge_h2i scatter (uses rec_h)
// ==========================================================================
#define PRE_I_BLOCKS ((N_I + 127) / 128)      // 3907
#define EDGE1_BLOCKS ((E1 + 127) / 128)       // 15625 (exact: 2e6 = 128*15625)
#define STRIDE_I 33

__global__ void __launch_bounds__(128)
k2_prei_edgeh(const float* __restrict__ x_indivi,
              const float* __restrict__ W_edge_i,  // [F_I, EF]
              const float* __restrict__ b_edge_i,  // [F_I]
              const float* __restrict__ W_root_h,  // [1, F_I]
              const float* __restrict__ W_root_i,  // [1, F_I]
              const float* __restrict__ bias_h,    // [1]
              const float* __restrict__ bias_i,    // [1]
              const float* __restrict__ ea1,
              const int*   __restrict__ src1,
              const int*   __restrict__ dst1,
              float* __restrict__ out)
{
    int t = threadIdx.x;

    if (blockIdx.x >= PRE_I_BLOCKS) {
        int e = (blockIdx.x - PRE_I_BLOCKS) * 128 + t;
        if (e < E1)
            edge_body(ea1, src1, dst1, g_rec_h, out, e);
        return;
    }

    // ----- indivi precompute (128 rows per block) -----
    __shared__ float sx[128 * STRIDE_I];    // 16.9 KB
    __shared__ float sW[F_I * EF];
    __shared__ float sb[F_I];
    __shared__ float sWr[F_I];
    __shared__ float sbias;

    sW[t]       = W_edge_i[t];
    sW[t + 128] = W_edge_i[t + 128];
    if (t < F_I) {
        sb[t]  = b_edge_i[t];
        sWr[t] = W_root_h[t] + W_root_i[t];
    }
    if (t == 0) sbias = bias_h[0] + bias_i[0];

    int base = blockIdx.x * 128;
    const float4* x4 = reinterpret_cast<const float4*>(x_indivi);
    long gbase = (long)base * (F_I / 4);
    long gmax  = (long)N_I * (F_I / 4);
#pragma unroll
    for (int i = 0; i < 8; i++) {
        long gidx = gbase + t + i * 128;
        if (gidx < gmax) {
            float4 v = x4[gidx];
            int loc = t + i * 128;
            int row = loc >> 3;                 // 8 float4 per row
            int col = loc & 7;
            float* p = sx + row * STRIDE_I + col * 4;
            p[0] = v.x; p[1] = v.y; p[2] = v.z; p[3] = v.w;
        }
    }
    __syncthreads();

    int n = base + t;
    if (n >= N_I) return;

    const float* xr = sx + t * STRIDE_I;
    float y[EF];
#pragma unroll
    for (int k = 0; k < EF; k++) y[k] = 0.f;
    float z = 0.f;
    float root = sbias;
#pragma unroll
    for (int f = 0; f < F_I; f++) {
        float xf = xr[f];
#pragma unroll
        for (int k = 0; k < EF; k++) y[k] = fmaf(xf, sW[f*EF + k], y[k]);
        z    = fmaf(xf, sb[f],  z);
        root = fmaf(xf, sWr[f], root);
    }

    float4* ro = reinterpret_cast<float4*>(g_rec_i + (size_t)n * 8);
    ro[0] = make_float4(pack2h(y[0], y[1]), pack2h(y[2], y[3]),
                        pack2h(y[4], y[5]), pack2h(y[6], y[7]));
    ro[1] = make_float4(z, 0.f, 0.f, 0.f);
    atomicAdd(out + n, root);                  // out concurrently hit by edges
}

// ==========================================================================
// K3: edge_i2i scatter (needs rec_i complete)
// ==========================================================================
__global__ void __launch_bounds__(256)
k3_edge_i(const float* __restrict__ ea2,
          const int*   __restrict__ src2,
          const int*   __restrict__ dst2,
          float* __restrict__ out)
{
    int e = blockIdx.x * 256 + threadIdx.x;
    if (e < E2)
        edge_body(ea2, src2, dst2, g_rec_i, out, e);
}

// ==========================================================================
extern "C" void kernel_launch(void* const* d_in, const int* in_sizes, int n_in,
                              void* d_out, int out_size)
{
    const float* x_indivi      = (const float*)d_in[0];
    const float* x_house       = (const float*)d_in[1];
    const float* edge_attr_h2i = (const float*)d_in[2];
    const float* edge_attr_i2i = (const float*)d_in[3];
    const float* W_edge_h2i    = (const float*)d_in[4];
    const float* b_edge_h2i    = (const float*)d_in[5];
    const float* W_edge_i2i    = (const float*)d_in[6];
    const float* b_edge_i2i    = (const float*)d_in[7];
    const float* W_root_h2i    = (const float*)d_in[8];
    const float* bias_h2i      = (const float*)d_in[9];
    const float* W_root_i2i    = (const float*)d_in[10];
    const float* bias_i2i      = (const float*)d_in[11];
    const int*   src_h2i       = (const int*)d_in[12];
    const int*   dst_h2i       = (const int*)d_in[13];
    const int*   src_i2i       = (const int*)d_in[14];
    const int*   dst_i2i       = (const int*)d_in[15];
    float* out = (float*)d_out;

    k1_house_zero<<<ZERO_BLOCKS + BLOCKS_H, 256>>>(
        x_house, W_edge_h2i, b_edge_h2i, out);

    k2_prei_edgeh<<<PRE_I_BLOCKS + EDGE1_BLOCKS, 128>>>(
        x_indivi, W_edge_i2i, b_edge_i2i, W_root_h2i, W_root_i2i,
        bias_h2i, bias_i2i, edge_attr_h2i, src_h2i, dst_h2i, out);

    k3_edge_i<<<(E2 + 255) / 256, 256>>>(
        edge_attr_i2i, src_i2i, dst_i2i, out);
}